// round 2
// baseline (speedup 1.0000x reference)
#include <cuda_runtime.h>
#include <math.h>

// Problem constants
#define B 64
#define S 512
#define D 1024
#define H 1024
#define G 4096  // 4*H

// Scratch (device globals - no allocation allowed in kernel_launch)
__device__ float g_xproj[(size_t)B * S * G];  // [B*S, 4H] = 512 MB
__device__ float g_h[2][B * H];               // ping-pong hidden state
__device__ float g_c[B * H];                  // cell state (in-place)

// ---------------------------------------------------------------------------
// Init: copy h0 / c0 into state buffers
// ---------------------------------------------------------------------------
__global__ void init_state(const float* __restrict__ h0,
                           const float* __restrict__ c0) {
    int i = blockIdx.x * blockDim.x + threadIdx.x;
    if (i < B * H) {
        g_h[0][i] = h0[i];
        g_c[i] = c0[i];
    }
}

// ---------------------------------------------------------------------------
// x_proj GEMM: C[M=B*S][G] = A[M][D] @ Wih[G][D]^T + bias_ih
// Both A and W are K-contiguous (NT gemm). 64x64 tile, TK=32, 256 threads,
// 4x4 microtile per thread.
// ---------------------------------------------------------------------------
#define TM 64
#define TN 64
#define TK 32

__global__ void __launch_bounds__(256, 2)
xproj_gemm(const float* __restrict__ A,
           const float* __restrict__ W,
           const float* __restrict__ bias) {
    __shared__ float sA[TM][TK + 1];
    __shared__ float sW[TN][TK + 1];

    int tid = threadIdx.x;
    int ty = tid >> 4;        // 0..15
    int tx = tid & 15;        // 0..15
    int mBase = blockIdx.y * TM;
    int nBase = blockIdx.x * TN;

    float acc[4][4] = {};

    for (int k0 = 0; k0 < D; k0 += TK) {
        // Load A tile (64x32) and W tile (64x32), coalesced
#pragma unroll
        for (int e = 0; e < 8; e++) {
            int i = tid + e * 256;
            int r = i >> 5;
            int k = i & 31;
            sA[r][k] = A[(size_t)(mBase + r) * D + (k0 + k)];
            sW[r][k] = W[(size_t)(nBase + r) * D + (k0 + k)];
        }
        __syncthreads();

#pragma unroll
        for (int k = 0; k < TK; k++) {
            float a[4], b[4];
#pragma unroll
            for (int i = 0; i < 4; i++) a[i] = sA[ty * 4 + i][k];
#pragma unroll
            for (int j = 0; j < 4; j++) b[j] = sW[tx * 4 + j][k];
#pragma unroll
            for (int i = 0; i < 4; i++)
#pragma unroll
                for (int j = 0; j < 4; j++)
                    acc[i][j] += a[i] * b[j];
        }
        __syncthreads();
    }

#pragma unroll
    for (int i = 0; i < 4; i++) {
        int m = mBase + ty * 4 + i;
#pragma unroll
        for (int j = 0; j < 4; j++) {
            int n = nBase + tx * 4 + j;
            g_xproj[(size_t)m * G + n] = acc[i][j] + bias[n];
        }
    }
}

// ---------------------------------------------------------------------------
// One LSTM timestep, fully fused:
//   gates[64, 4H-slice] = h_prev @ Whh^T  (+ x_proj + bias_hh)
//   pointwise i,f,g,o -> c,h update -> write h_next, c, outputs[:, t, :]
// Each block owns HT=8 hidden columns, i.e. NT=32 gate columns (4 gates x 8),
// for all 64 batch rows. Grid = H/HT = 128 blocks, 256 threads.
// ---------------------------------------------------------------------------
#define HT 8
#define NT 32

__global__ void __launch_bounds__(256, 2)
lstm_step(const float* __restrict__ W_hh,
          const float* __restrict__ bias_hh,
          float* __restrict__ out, int t) {
    __shared__ float sH[B][TK + 1];
    __shared__ float sW[NT][TK + 1];
    __shared__ float sG[B][NT + 1];

    const float* __restrict__ h_prev = g_h[t & 1];
    float* __restrict__ h_next = g_h[(t + 1) & 1];

    int tid = threadIdx.x;
    int hbase = blockIdx.x * HT;
    int n = tid & 31;          // gate column within tile (0..31)
    int m0 = (tid >> 5) * 8;   // first batch row for this thread

    float acc[8] = {};

    for (int k0 = 0; k0 < H; k0 += TK) {
        // Load h tile: 64x32
#pragma unroll
        for (int e = 0; e < 8; e++) {
            int i = tid + e * 256;
            int r = i >> 5;
            int k = i & 31;
            sH[r][k] = h_prev[r * H + (k0 + k)];
        }
        // Load Whh tile: 32 gate rows x 32 k
#pragma unroll
        for (int e = 0; e < 4; e++) {
            int i = tid + e * 256;
            int r = i >> 5;   // gate column index (0..31)
            int k = i & 31;
            int q = r >> 3;   // gate (0..3)
            int j = r & 7;    // hidden column within tile
            sW[r][k] = W_hh[(size_t)(q * H + hbase + j) * H + (k0 + k)];
        }
        __syncthreads();

#pragma unroll
        for (int k = 0; k < TK; k++) {
            float wv = sW[n][k];
#pragma unroll
            for (int r = 0; r < 8; r++)
                acc[r] += sH[m0 + r][k] * wv;
        }
        __syncthreads();
    }

#pragma unroll
    for (int r = 0; r < 8; r++) sG[m0 + r][n] = acc[r];
    __syncthreads();

    // Pointwise: 64 batches x 8 hidden columns = 512 elements, 2 per thread
#pragma unroll
    for (int e = 0; e < 2; e++) {
        int p = tid + e * 256;
        int b = p >> 3;
        int j = p & 7;

        size_t xbase = ((size_t)b * S + t) * G;
        int ci = 0 * H + hbase + j;
        int cf = 1 * H + hbase + j;
        int cg = 2 * H + hbase + j;
        int co = 3 * H + hbase + j;

        float gi = sG[b][0 + j]  + g_xproj[xbase + ci] + bias_hh[ci];
        float gf = sG[b][8 + j]  + g_xproj[xbase + cf] + bias_hh[cf];
        float gg = sG[b][16 + j] + g_xproj[xbase + cg] + bias_hh[cg];
        float go = sG[b][24 + j] + g_xproj[xbase + co] + bias_hh[co];

        float iv = 1.0f / (1.0f + expf(-gi));
        float fv = 1.0f / (1.0f + expf(-gf));
        float gv = tanhf(gg);
        float ov = 1.0f / (1.0f + expf(-go));

        int idx = b * H + hbase + j;
        float c_new = fv * g_c[idx] + iv * gv;
        g_c[idx] = c_new;
        float h_new = ov * tanhf(c_new);
        h_next[idx] = h_new;
        out[((size_t)b * S + t) * H + (hbase + j)] = h_new;
    }
}

// ---------------------------------------------------------------------------
// Finalize: write hn, cn after outputs. S is even -> final h is in g_h[0].
// ---------------------------------------------------------------------------
__global__ void finalize(float* __restrict__ out) {
    int i = blockIdx.x * blockDim.x + threadIdx.x;
    if (i < B * H) {
        size_t tail = (size_t)B * S * H;
        out[tail + i] = g_h[0][i];
        out[tail + (size_t)B * H + i] = g_c[i];
    }
}

// ---------------------------------------------------------------------------
// Launch
// ---------------------------------------------------------------------------
extern "C" void kernel_launch(void* const* d_in, const int* in_sizes, int n_in,
                              void* d_out, int out_size) {
    (void)in_sizes; (void)n_in; (void)out_size;

    const float* inputs = (const float*)d_in[0];  // [B, S, D]
    const float* h0     = (const float*)d_in[1];  // [1, B, H]
    const float* c0     = (const float*)d_in[2];  // [1, B, H]
    const float* wih    = (const float*)d_in[3];  // [4H, D]
    const float* whh    = (const float*)d_in[4];  // [4H, H]
    const float* bih    = (const float*)d_in[5];  // [4H]
    const float* bhh    = (const float*)d_in[6];  // [4H]
    float* out = (float*)d_out;

    init_state<<<(B * H + 255) / 256, 256>>>(h0, c0);

    dim3 gx(G / TN, (B * S) / TM);  // 64 x 512 blocks
    xproj_gemm<<<gx, 256>>>(inputs, wih, bih);

    for (int t = 0; t < S; t++) {
        lstm_step<<<H / HT, 256>>>(whh, bhh, out, t);
    }

    finalize<<<(B * H + 255) / 256, 256>>>(out);
}

// round 4
// speedup vs baseline: 2.0296x; 2.0296x over previous
#include <cuda_runtime.h>
#include <math.h>
#include <stdint.h>

// Problem constants
#define B 64
#define S 512
#define D 1024
#define H 1024
#define G 4096  // 4*H

// Step-kernel geometry: 128 CTAs, each owns 32 gate rows (4 gates x 8 hid cols)
#define NCTA 128
#define THREADS 256
#define NCHUNK 8               // K chunks of 128
#define KSTEPS_PER_CHUNK 16    // k8 steps per chunk
// A chunk: 16 ksteps * 2 mblk * 32 lanes * 4 floats = 4096 words = 16KB
#define A_CHUNK_WORDS 4096
// B chunk: 16 ksteps * 4 nblk * 32 lanes * 4 floats = 8192 words = 32KB
#define B_CHUNK_WORDS 8192
#define DYN_SMEM_BYTES ((2 * A_CHUNK_WORDS + 2 * B_CHUNK_WORDS) * 4)  // 96KB

// Device scratch (no allocation allowed)
__device__ float    g_xproj[(size_t)B * S * G];                     // [B*S, 4H]
__device__ uint32_t g_wpack[(size_t)NCTA * NCHUNK * A_CHUNK_WORDS]; // Whh tf32, fragment-packed
__device__ uint32_t g_hpack[2][NCHUNK * B_CHUNK_WORDS];             // h tf32, fragment-packed (ping-pong)
__device__ float    g_c[B * H];                                     // cell state

// ---------------------------------------------------------------------------
// Helpers
// ---------------------------------------------------------------------------
__device__ __forceinline__ uint32_t smem_u32(const void* p) {
    uint32_t a;
    asm("{ .reg .u64 t; cvta.to.shared.u64 t, %1; cvt.u32.u64 %0, t; }"
        : "=r"(a) : "l"(p));
    return a;
}

__device__ __forceinline__ uint32_t f2tf32(float f) {
    uint32_t r;
    asm("cvt.rna.tf32.f32 %0, %1;" : "=r"(r) : "f"(f));
    return r;
}

#define CP_ASYNC16(dst, src) \
    asm volatile("cp.async.cg.shared.global [%0], [%1], 16;" :: "r"(dst), "l"(src) : "memory")
#define CP_COMMIT() asm volatile("cp.async.commit_group;" ::: "memory")
#define CP_WAIT(n)  asm volatile("cp.async.wait_group %0;" :: "n"(n) : "memory")

#define MMA_TF32(c0, c1, c2, c3, a0, a1, a2, a3, b0, b1)                     \
    asm volatile("mma.sync.aligned.m16n8k8.row.col.f32.tf32.tf32.f32 "       \
                 "{%0,%1,%2,%3}, {%4,%5,%6,%7}, {%8,%9}, {%0,%1,%2,%3};"     \
                 : "+f"(c0), "+f"(c1), "+f"(c2), "+f"(c3)                    \
                 : "r"(a0), "r"(a1), "r"(a2), "r"(a3), "r"(b0), "r"(b1))

// ---------------------------------------------------------------------------
// One-time prep: Whh fp32 -> tf32 in exact per-lane A-fragment order.
// Layout: g_wpack[ct][kstep(128)][mblk(2)][lane(32)][a(4)]
//   a: row16 = lane/4 + 8*(a&1), kofs = lane%4 + 4*(a>>1)
//   tile row r = mblk*16 + row16; gate q = r>>3; hid j = r&7
//   global: W[q*H + ct*8 + j][kstep*8 + kofs]
// ---------------------------------------------------------------------------
__global__ void prep_wpack(const float* __restrict__ whh) {
    int idx = blockIdx.x * 256 + threadIdx.x;   // 0 .. 4M-1
    int a     = idx & 3;
    int lane  = (idx >> 2) & 31;
    int mblk  = (idx >> 7) & 1;
    int kstep = (idx >> 8) & 127;
    int ct    = idx >> 15;

    int row16 = (lane >> 2) + 8 * (a & 1);
    int kofs  = (lane & 3) + 4 * (a >> 1);
    int r = mblk * 16 + row16;
    int q = r >> 3;
    int j = r & 7;
    int grow = q * H + ct * 8 + j;
    int k = kstep * 8 + kofs;
    g_wpack[idx] = f2tf32(whh[(size_t)grow * H + k]);
}

// ---------------------------------------------------------------------------
// Init: c0 -> g_c ; h0 -> B-fragment-packed tf32 (buffer 0).
// B pack layout: [kstep(128)][nblk(4)][lane(32)][f(4)] where f = khalf*2 + jb
//   value = h[n = nblk*16 + jb*8 + lane/4][k = kstep*8 + lane%4 + 4*khalf]
// ---------------------------------------------------------------------------
__device__ __forceinline__ uint32_t hpack_addr(int b, int hid) {
    int kstep = hid >> 3, kk = hid & 7;
    int khalf = kk >> 2, kfrac = kk & 3;
    int nblk = b >> 4, rem = b & 15;
    int jb = rem >> 3, trow = rem & 7;
    int lane = trow * 4 + kfrac;
    int f = khalf * 2 + jb;
    return (uint32_t)(((kstep * 4 + nblk) * 32 + lane) * 4 + f);
}

__global__ void init_state(const float* __restrict__ h0,
                           const float* __restrict__ c0) {
    int i = blockIdx.x * blockDim.x + threadIdx.x;
    if (i < B * H) {
        g_c[i] = c0[i];
        int b = i >> 10, hid = i & 1023;
        g_hpack[0][hpack_addr(b, hid)] = f2tf32(h0[i]);
    }
}

// ---------------------------------------------------------------------------
// x_proj GEMM (SIMT fp32, unchanged from passing baseline)
// ---------------------------------------------------------------------------
#define TM 64
#define TN 64
#define TK 32

__global__ void __launch_bounds__(256, 2)
xproj_gemm(const float* __restrict__ A,
           const float* __restrict__ W,
           const float* __restrict__ bias) {
    __shared__ float sA[TM][TK + 1];
    __shared__ float sW[TN][TK + 1];

    int tid = threadIdx.x;
    int ty = tid >> 4;
    int tx = tid & 15;
    int mBase = blockIdx.y * TM;
    int nBase = blockIdx.x * TN;

    float acc[4][4] = {};

    for (int k0 = 0; k0 < D; k0 += TK) {
#pragma unroll
        for (int e = 0; e < 8; e++) {
            int i = tid + e * 256;
            int r = i >> 5;
            int k = i & 31;
            sA[r][k] = A[(size_t)(mBase + r) * D + (k0 + k)];
            sW[r][k] = W[(size_t)(nBase + r) * D + (k0 + k)];
        }
        __syncthreads();
#pragma unroll
        for (int k = 0; k < TK; k++) {
            float a[4], b[4];
#pragma unroll
            for (int i = 0; i < 4; i++) a[i] = sA[ty * 4 + i][k];
#pragma unroll
            for (int j = 0; j < 4; j++) b[j] = sW[tx * 4 + j][k];
#pragma unroll
            for (int i = 0; i < 4; i++)
#pragma unroll
                for (int j = 0; j < 4; j++)
                    acc[i][j] += a[i] * b[j];
        }
        __syncthreads();
    }

#pragma unroll
    for (int i = 0; i < 4; i++) {
        int m = mBase + ty * 4 + i;
#pragma unroll
        for (int j = 0; j < 4; j++) {
            int n = nBase + tx * 4 + j;
            g_xproj[(size_t)m * G + n] = acc[i][j] + bias[n];
        }
    }
}

// ---------------------------------------------------------------------------
// LSTM step via warp-level tf32 mma.sync.
// CTA bx: gates^T tile [32 rows x 64 batch] = Whh_rows(bx) @ h^T, K=1024.
// 8 warps: warp w -> mblk = w&1 (m16), nblk = w>>1 (n16, 2 n8 frags).
// Inner loop per k8: 1 LDS.128 (A frag) + 1 LDS.128 (2 B frags) + 2 HMMA.
// ---------------------------------------------------------------------------
__global__ void __launch_bounds__(THREADS, 1)
lstm_step_mma(const float* __restrict__ bias_hh, float* __restrict__ out, int t) {
    extern __shared__ __align__(16) uint32_t dynsmem[];
    uint4* bufA[2] = { (uint4*)dynsmem, (uint4*)(dynsmem + A_CHUNK_WORDS) };
    uint4* bufB[2] = { (uint4*)(dynsmem + 2 * A_CHUNK_WORDS),
                       (uint4*)(dynsmem + 2 * A_CHUNK_WORDS + B_CHUNK_WORDS) };

    int tid = threadIdx.x;
    int wid = tid >> 5;
    int lane = tid & 31;
    int bx = blockIdx.x;
    int mblk = wid & 1;
    int nblk = wid >> 1;

    const uint32_t* gA = g_wpack + (size_t)bx * NCHUNK * A_CHUNK_WORDS;
    const uint32_t* gB = g_hpack[t & 1];

    uint32_t sA_addr[2] = { smem_u32(bufA[0]), smem_u32(bufA[1]) };
    uint32_t sB_addr[2] = { smem_u32(bufB[0]), smem_u32(bufB[1]) };

    // Prologue: async-load chunk 0
    {
#pragma unroll
        for (int i = 0; i < 4; i++) {
            int l = tid + i * 256;
            CP_ASYNC16(sA_addr[0] + l * 16, (const char*)(gA) + l * 16);
        }
#pragma unroll
        for (int i = 0; i < 8; i++) {
            int l = tid + i * 256;
            CP_ASYNC16(sB_addr[0] + l * 16, (const char*)(gB) + l * 16);
        }
        CP_COMMIT();
    }

    float c00 = 0.f, c01 = 0.f, c02 = 0.f, c03 = 0.f;  // n8 frag 0
    float c10 = 0.f, c11 = 0.f, c12 = 0.f, c13 = 0.f;  // n8 frag 1

    for (int c = 0; c < NCHUNK; c++) {
        if (c < NCHUNK - 1) {
            int nb = (c + 1) & 1;
            const char* srcA = (const char*)(gA + (size_t)(c + 1) * A_CHUNK_WORDS);
            const char* srcB = (const char*)(gB + (size_t)(c + 1) * B_CHUNK_WORDS);
#pragma unroll
            for (int i = 0; i < 4; i++) {
                int l = tid + i * 256;
                CP_ASYNC16(sA_addr[nb] + l * 16, srcA + l * 16);
            }
#pragma unroll
            for (int i = 0; i < 8; i++) {
                int l = tid + i * 256;
                CP_ASYNC16(sB_addr[nb] + l * 16, srcB + l * 16);
            }
            CP_COMMIT();
            CP_WAIT(1);
        } else {
            CP_WAIT(0);
        }
        __syncthreads();

        const uint4* cA = bufA[c & 1];
        const uint4* cB = bufB[c & 1];
        int aIdx = mblk * 32 + lane;   // + ks*64
        int bIdx = nblk * 32 + lane;   // + ks*128
#pragma unroll
        for (int ks = 0; ks < KSTEPS_PER_CHUNK; ks++) {
            uint4 av = cA[aIdx + ks * 64];
            uint4 bv = cB[bIdx + ks * 128];
            MMA_TF32(c00, c01, c02, c03, av.x, av.y, av.z, av.w, bv.x, bv.z);
            MMA_TF32(c10, c11, c12, c13, av.x, av.y, av.z, av.w, bv.y, bv.w);
        }
        __syncthreads();
    }

    // Exchange C through smem: sG[row 32][batch 64], stride 66 (even, 8B aligned)
    float* sG = (float*)dynsmem;  // 32*66*4 = 8448B, overlays bufA[0]
    {
        int r0 = mblk * 16 + (lane >> 2);
        int col = nblk * 16 + (lane & 3) * 2;
        // frag 0 (cols +0), frag 1 (cols +8)
        *(float2*)&sG[r0 * 66 + col]            = make_float2(c00, c01);
        *(float2*)&sG[(r0 + 8) * 66 + col]      = make_float2(c02, c03);
        *(float2*)&sG[r0 * 66 + col + 8]        = make_float2(c10, c11);
        *(float2*)&sG[(r0 + 8) * 66 + col + 8]  = make_float2(c12, c13);
    }
    __syncthreads();

    // Pointwise: CTA owns hid in [bx*8, bx*8+8), all 64 batches = 512 elems.
    uint32_t* hnext = g_hpack[(t + 1) & 1];
#pragma unroll
    for (int e = 0; e < 2; e++) {
        int p = tid + e * 256;
        int b = p >> 3;
        int j = p & 7;
        int hid = bx * 8 + j;

        size_t xb = ((size_t)b * S + t) * G + hid;
        float gi = sG[(0 * 8 + j) * 66 + b] + g_xproj[xb]         + __ldg(&bias_hh[hid]);
        float gf = sG[(1 * 8 + j) * 66 + b] + g_xproj[xb + H]     + __ldg(&bias_hh[H + hid]);
        float gg = sG[(2 * 8 + j) * 66 + b] + g_xproj[xb + 2 * H] + __ldg(&bias_hh[2 * H + hid]);
        float go = sG[(3 * 8 + j) * 66 + b] + g_xproj[xb + 3 * H] + __ldg(&bias_hh[3 * H + hid]);

        float iv = 1.0f / (1.0f + expf(-gi));
        float fv = 1.0f / (1.0f + expf(-gf));
        float gv = tanhf(gg);
        float ov = 1.0f / (1.0f + expf(-go));

        int ci = b * H + hid;
        float c_new = fv * g_c[ci] + iv * gv;
        g_c[ci] = c_new;
        float hv = ov * tanhf(c_new);

        out[((size_t)b * S + t) * H + hid] = hv;
        hnext[hpack_addr(b, hid)] = f2tf32(hv);
    }
}

// ---------------------------------------------------------------------------
// Finalize: hn = out[:, S-1, :], cn = g_c
// ---------------------------------------------------------------------------
__global__ void finalize(float* __restrict__ out) {
    int i = blockIdx.x * blockDim.x + threadIdx.x;
    if (i < B * H) {
        int b = i >> 10, hid = i & 1023;
        size_t tail = (size_t)B * S * H;
        out[tail + i] = out[((size_t)b * S + (S - 1)) * H + hid];
        out[tail + (size_t)B * H + i] = g_c[i];
    }
}

// ---------------------------------------------------------------------------
// Launch
// ---------------------------------------------------------------------------
extern "C" void kernel_launch(void* const* d_in, const int* in_sizes, int n_in,
                              void* d_out, int out_size) {
    (void)in_sizes; (void)n_in; (void)out_size;

    const float* inputs = (const float*)d_in[0];  // [B, S, D]
    const float* h0     = (const float*)d_in[1];  // [1, B, H]
    const float* c0     = (const float*)d_in[2];  // [1, B, H]
    const float* wih    = (const float*)d_in[3];  // [4H, D]
    const float* whh    = (const float*)d_in[4];  // [4H, H]
    const float* bih    = (const float*)d_in[5];  // [4H]
    const float* bhh    = (const float*)d_in[6];  // [4H]
    float* out = (float*)d_out;

    static int attr_done = 0;
    if (!attr_done) {
        cudaFuncSetAttribute(lstm_step_mma,
                             cudaFuncAttributeMaxDynamicSharedMemorySize,
                             DYN_SMEM_BYTES);
        attr_done = 1;
    }

    init_state<<<(B * H + 255) / 256, 256>>>(h0, c0);
    prep_wpack<<<(G * H) / 256, 256>>>(whh);

    dim3 gx(G / TN, (B * S) / TM);
    xproj_gemm<<<gx, 256>>>(inputs, wih, bih);

    for (int t = 0; t < S; t++) {
        lstm_step_mma<<<NCTA, THREADS, DYN_SMEM_BYTES>>>(bhh, out, t);
    }

    finalize<<<(B * H + 255) / 256, 256>>>(out);
}

// round 6
// speedup vs baseline: 2.3387x; 1.1523x over previous
#include <cuda_runtime.h>
#include <math.h>
#include <stdint.h>

// Problem constants
#define B 64
#define S 512
#define D 1024
#define H 1024
#define G 4096  // 4*H

// Persistent step kernel: 128 CTAs, each owns 32 gate rows (4 gates x 8 hid)
#define NCTA 128
#define THREADS 256
// Weight slab per CTA: 128 ksteps * 2 mblk * 32 lanes * 16B = 8192 uint4 = 128KB
#define W_SLAB_UINT4 8192
#define SG_STRIDE 66
#define DYN_SMEM_BYTES (W_SLAB_UINT4 * 16 + 32 * SG_STRIDE * 4)  // 139520

// Device scratch (no allocation allowed)
__device__ float    g_xproj[(size_t)B * S * G];                  // [B*S, 4H]
__device__ uint32_t g_wpack[(size_t)NCTA * W_SLAB_UINT4 * 4];    // Whh tf32, fragment-packed
__device__ uint32_t g_hpack[2][128 * 4 * 32 * 4];                // h tf32, fragment-packed (ping-pong)
__device__ float    g_c[B * H];                                  // cell state (start/end only)
__device__ unsigned g_bar;                                       // global step barrier

// ---------------------------------------------------------------------------
// Helpers
// ---------------------------------------------------------------------------
__device__ __forceinline__ uint32_t f2tf32(float f) {
    uint32_t r;
    asm("cvt.rna.tf32.f32 %0, %1;" : "=r"(r) : "f"(f));
    return r;
}

#define MMA_TF32(c0, c1, c2, c3, a0, a1, a2, a3, b0, b1)                     \
    asm volatile("mma.sync.aligned.m16n8k8.row.col.f32.tf32.tf32.f32 "       \
                 "{%0,%1,%2,%3}, {%4,%5,%6,%7}, {%8,%9}, {%0,%1,%2,%3};"     \
                 : "+f"(c0), "+f"(c1), "+f"(c2), "+f"(c3)                    \
                 : "r"(a0), "r"(a1), "r"(a2), "r"(a3), "r"(b0), "r"(b1))

// ---------------------------------------------------------------------------
// One-time prep: Whh fp32 -> tf32 in exact per-lane A-fragment order.
// Layout: g_wpack[ct][kstep(128)][mblk(2)][lane(32)][a(4)]
//   a: row16 = lane/4 + 8*(a&1), kofs = lane%4 + 4*(a>>1)
//   tile row r = mblk*16 + row16; gate q = r>>3; hid j = r&7
//   global: W[q*H + ct*8 + j][kstep*8 + kofs]
// ---------------------------------------------------------------------------
__global__ void prep_wpack(const float* __restrict__ whh) {
    int idx = blockIdx.x * 256 + threadIdx.x;   // 0 .. 4M-1
    int a     = idx & 3;
    int lane  = (idx >> 2) & 31;
    int mblk  = (idx >> 7) & 1;
    int kstep = (idx >> 8) & 127;
    int ct    = idx >> 15;

    int row16 = (lane >> 2) + 8 * (a & 1);
    int kofs  = (lane & 3) + 4 * (a >> 1);
    int r = mblk * 16 + row16;
    int q = r >> 3;
    int j = r & 7;
    int grow = q * H + ct * 8 + j;
    int k = kstep * 8 + kofs;
    g_wpack[idx] = f2tf32(whh[(size_t)grow * H + k]);
}

// ---------------------------------------------------------------------------
// B-fragment pack address: [kstep(128)][nblk(4)][lane(32)][f(4)], f=khalf*2+jb
//   value = h[n = nblk*16 + jb*8 + lane/4][k = kstep*8 + lane%4 + 4*khalf]
// ---------------------------------------------------------------------------
__device__ __forceinline__ uint32_t hpack_addr(int b, int hid) {
    int kstep = hid >> 3, kk = hid & 7;
    int khalf = kk >> 2, kfrac = kk & 3;
    int nblk = b >> 4, rem = b & 15;
    int jb = rem >> 3, trow = rem & 7;
    int lane = trow * 4 + kfrac;
    int f = khalf * 2 + jb;
    return (uint32_t)(((kstep * 4 + nblk) * 32 + lane) * 4 + f);
}

__global__ void init_state(const float* __restrict__ h0,
                           const float* __restrict__ c0) {
    int i = blockIdx.x * blockDim.x + threadIdx.x;
    if (i == 0) g_bar = 0u;
    if (i < B * H) {
        g_c[i] = c0[i];
        int b = i >> 10, hid = i & 1023;
        g_hpack[0][hpack_addr(b, hid)] = f2tf32(h0[i]);
    }
}

// ---------------------------------------------------------------------------
// x_proj GEMM (SIMT fp32, unchanged)
// ---------------------------------------------------------------------------
#define TM 64
#define TN 64
#define TK 32

__global__ void __launch_bounds__(256, 2)
xproj_gemm(const float* __restrict__ A,
           const float* __restrict__ W,
           const float* __restrict__ bias) {
    __shared__ float sA[TM][TK + 1];
    __shared__ float sW[TN][TK + 1];

    int tid = threadIdx.x;
    int ty = tid >> 4;
    int tx = tid & 15;
    int mBase = blockIdx.y * TM;
    int nBase = blockIdx.x * TN;

    float acc[4][4] = {};

    for (int k0 = 0; k0 < D; k0 += TK) {
#pragma unroll
        for (int e = 0; e < 8; e++) {
            int i = tid + e * 256;
            int r = i >> 5;
            int k = i & 31;
            sA[r][k] = A[(size_t)(mBase + r) * D + (k0 + k)];
            sW[r][k] = W[(size_t)(nBase + r) * D + (k0 + k)];
        }
        __syncthreads();
#pragma unroll
        for (int k = 0; k < TK; k++) {
            float a[4], b[4];
#pragma unroll
            for (int i = 0; i < 4; i++) a[i] = sA[ty * 4 + i][k];
#pragma unroll
            for (int j = 0; j < 4; j++) b[j] = sW[tx * 4 + j][k];
#pragma unroll
            for (int i = 0; i < 4; i++)
#pragma unroll
                for (int j = 0; j < 4; j++)
                    acc[i][j] += a[i] * b[j];
        }
        __syncthreads();
    }

#pragma unroll
    for (int i = 0; i < 4; i++) {
        int m = mBase + ty * 4 + i;
#pragma unroll
        for (int j = 0; j < 4; j++) {
            int n = nBase + tx * 4 + j;
            g_xproj[(size_t)m * G + n] = acc[i][j] + bias[n];
        }
    }
}

// ---------------------------------------------------------------------------
// Persistent LSTM: all 512 steps in one launch.
// - Weight slab lives in SMEM for the whole sequence (loaded once).
// - c state lives in registers for the whole sequence.
// - B fragments read with __ldcg (L2-coherent; persistent kernel => no
//   per-launch L1 flush, and hpack is rewritten by peer CTAs every step).
// - Device-wide barrier (L2 atomic counter) between steps, with release
//   fence before arrive and acquire fence after the spin.
// ---------------------------------------------------------------------------
__global__ void __launch_bounds__(THREADS, 1)
lstm_persist(const float* __restrict__ bias_hh, float* __restrict__ out) {
    extern __shared__ __align__(16) uint4 smem4[];
    uint4* sW = smem4;                              // 8192 uint4 weight slab
    float* sG = (float*)(smem4 + W_SLAB_UINT4);     // 32 x 66 exchange

    int tid = threadIdx.x;
    int wid = tid >> 5;
    int lane = tid & 31;
    int bx = blockIdx.x;
    int mblk = wid & 1;
    int nblk = wid >> 1;

    // Load weight slab once
    const uint4* gW = (const uint4*)g_wpack + (size_t)bx * W_SLAB_UINT4;
#pragma unroll
    for (int i = 0; i < W_SLAB_UINT4 / THREADS; i++)
        sW[tid + i * THREADS] = gW[tid + i * THREADS];

    // Pointwise mapping constants: thread owns (b0, hid) and (b0+32, hid)
    int j = tid & 7;
    int b0 = tid >> 3;            // 0..31
    int hid = bx * 8 + j;
    float bi0 = bias_hh[hid];
    float bi1 = bias_hh[H + hid];
    float bi2 = bias_hh[2 * H + hid];
    float bi3 = bias_hh[3 * H + hid];
    float creg0 = g_c[b0 * H + hid];
    float creg1 = g_c[(b0 + 32) * H + hid];

    __syncthreads();

    int bIdx = nblk * 32 + lane;
    int aBase = mblk * 32 + lane;

    for (int t = 0; t < S; t++) {
        // Prefetch this step's xproj contributions (DRAM, hidden under MMA)
        size_t xb0 = ((size_t)b0 * S + t) * G + hid;
        size_t xb1 = ((size_t)(b0 + 32) * S + t) * G + hid;
        float xp00 = __ldg(&g_xproj[xb0]);
        float xp01 = __ldg(&g_xproj[xb0 + H]);
        float xp02 = __ldg(&g_xproj[xb0 + 2 * H]);
        float xp03 = __ldg(&g_xproj[xb0 + 3 * H]);
        float xp10 = __ldg(&g_xproj[xb1]);
        float xp11 = __ldg(&g_xproj[xb1 + H]);
        float xp12 = __ldg(&g_xproj[xb1 + 2 * H]);
        float xp13 = __ldg(&g_xproj[xb1 + 3 * H]);

        const uint4* gB4 = (const uint4*)g_hpack[t & 1];

        float c00 = 0.f, c01 = 0.f, c02 = 0.f, c03 = 0.f;
        float c10 = 0.f, c11 = 0.f, c12 = 0.f, c13 = 0.f;

        uint4 bvA[8], bvB[8];
#pragma unroll
        for (int k = 0; k < 8; k++) bvA[k] = __ldcg(&gB4[k * 128 + bIdx]);

#pragma unroll 1
        for (int ks0 = 0; ks0 < 128; ks0 += 16) {
#pragma unroll
            for (int k = 0; k < 8; k++)
                bvB[k] = __ldcg(&gB4[(ks0 + 8 + k) * 128 + bIdx]);
#pragma unroll
            for (int k = 0; k < 8; k++) {
                uint4 av = sW[(ks0 + k) * 64 + aBase];
                MMA_TF32(c00, c01, c02, c03, av.x, av.y, av.z, av.w, bvA[k].x, bvA[k].z);
                MMA_TF32(c10, c11, c12, c13, av.x, av.y, av.z, av.w, bvA[k].y, bvA[k].w);
            }
            if (ks0 + 16 < 128) {
                // Prefetch ksteps [ks0+16, ks0+24) for the NEXT iteration's
                // first MMA half. (Round-5 bug: this read ks0+24.. -> off by 8.)
#pragma unroll
                for (int k = 0; k < 8; k++)
                    bvA[k] = __ldcg(&gB4[(ks0 + 16 + k) * 128 + bIdx]);
            }
#pragma unroll
            for (int k = 0; k < 8; k++) {
                uint4 av = sW[(ks0 + 8 + k) * 64 + aBase];
                MMA_TF32(c00, c01, c02, c03, av.x, av.y, av.z, av.w, bvB[k].x, bvB[k].z);
                MMA_TF32(c10, c11, c12, c13, av.x, av.y, av.z, av.w, bvB[k].y, bvB[k].w);
            }
        }

        // Exchange fragments through SMEM
        {
            int r0 = mblk * 16 + (lane >> 2);
            int col = nblk * 16 + (lane & 3) * 2;
            *(float2*)&sG[r0 * SG_STRIDE + col]           = make_float2(c00, c01);
            *(float2*)&sG[(r0 + 8) * SG_STRIDE + col]     = make_float2(c02, c03);
            *(float2*)&sG[r0 * SG_STRIDE + col + 8]       = make_float2(c10, c11);
            *(float2*)&sG[(r0 + 8) * SG_STRIDE + col + 8] = make_float2(c12, c13);
        }
        __syncthreads();

        uint32_t* hnext = g_hpack[(t + 1) & 1];
        // Pointwise, element 0: (b0, hid)
        {
            float gi = sG[(0 * 8 + j) * SG_STRIDE + b0] + xp00 + bi0;
            float gf = sG[(1 * 8 + j) * SG_STRIDE + b0] + xp01 + bi1;
            float gg = sG[(2 * 8 + j) * SG_STRIDE + b0] + xp02 + bi2;
            float go = sG[(3 * 8 + j) * SG_STRIDE + b0] + xp03 + bi3;
            float iv = 1.0f / (1.0f + expf(-gi));
            float fv = 1.0f / (1.0f + expf(-gf));
            float gv = tanhf(gg);
            float ov = 1.0f / (1.0f + expf(-go));
            creg0 = fv * creg0 + iv * gv;
            float hv = ov * tanhf(creg0);
            out[((size_t)b0 * S + t) * H + hid] = hv;
            hnext[hpack_addr(b0, hid)] = f2tf32(hv);
        }
        // Pointwise, element 1: (b0+32, hid)
        {
            float gi = sG[(0 * 8 + j) * SG_STRIDE + b0 + 32] + xp10 + bi0;
            float gf = sG[(1 * 8 + j) * SG_STRIDE + b0 + 32] + xp11 + bi1;
            float gg = sG[(2 * 8 + j) * SG_STRIDE + b0 + 32] + xp12 + bi2;
            float go = sG[(3 * 8 + j) * SG_STRIDE + b0 + 32] + xp13 + bi3;
            float iv = 1.0f / (1.0f + expf(-gi));
            float fv = 1.0f / (1.0f + expf(-gf));
            float gv = tanhf(gg);
            float ov = 1.0f / (1.0f + expf(-go));
            creg1 = fv * creg1 + iv * gv;
            float hv = ov * tanhf(creg1);
            out[((size_t)(b0 + 32) * S + t) * H + hid] = hv;
            hnext[hpack_addr(b0 + 32, hid)] = f2tf32(hv);
        }

        // Device-wide step barrier: release writes, arrive, spin, acquire.
        __threadfence();
        __syncthreads();
        if (tid == 0) {
            atomicAdd(&g_bar, 1u);
            unsigned target = (unsigned)(NCTA * (t + 1));
            while (atomicAdd(&g_bar, 0u) < target) {
                __nanosleep(32);
            }
            __threadfence();   // acquire side
        }
        __syncthreads();
    }

    // Write back final c for finalize
    g_c[b0 * H + hid] = creg0;
    g_c[(b0 + 32) * H + hid] = creg1;
}

// ---------------------------------------------------------------------------
// Finalize: hn = out[:, S-1, :], cn = g_c
// ---------------------------------------------------------------------------
__global__ void finalize(float* __restrict__ out) {
    int i = blockIdx.x * blockDim.x + threadIdx.x;
    if (i < B * H) {
        int b = i >> 10, hid = i & 1023;
        size_t tail = (size_t)B * S * H;
        out[tail + i] = out[((size_t)b * S + (S - 1)) * H + hid];
        out[tail + (size_t)B * H + i] = g_c[i];
    }
}

// ---------------------------------------------------------------------------
// Launch
// ---------------------------------------------------------------------------
extern "C" void kernel_launch(void* const* d_in, const int* in_sizes, int n_in,
                              void* d_out, int out_size) {
    (void)in_sizes; (void)n_in; (void)out_size;

    const float* inputs = (const float*)d_in[0];  // [B, S, D]
    const float* h0     = (const float*)d_in[1];  // [1, B, H]
    const float* c0     = (const float*)d_in[2];  // [1, B, H]
    const float* wih    = (const float*)d_in[3];  // [4H, D]
    const float* whh    = (const float*)d_in[4];  // [4H, H]
    const float* bih    = (const float*)d_in[5];  // [4H]
    const float* bhh    = (const float*)d_in[6];  // [4H]
    float* out = (float*)d_out;

    cudaFuncSetAttribute(lstm_persist,
                         cudaFuncAttributeMaxDynamicSharedMemorySize,
                         DYN_SMEM_BYTES);

    init_state<<<(B * H + 255) / 256, 256>>>(h0, c0);
    prep_wpack<<<(G * H) / 256, 256>>>(whh);

    dim3 gx(G / TN, (B * S) / TM);
    xproj_gemm<<<gx, 256>>>(inputs, wih, bih);

    lstm_persist<<<NCTA, THREADS, DYN_SMEM_BYTES>>>(bhh, out);

    finalize<<<(B * H + 255) / 256, 256>>>(out);
}

// round 7
// speedup vs baseline: 4.5788x; 1.9578x over previous
#include <cuda_runtime.h>
#include <math.h>
#include <stdint.h>

// Problem constants
#define B 64
#define S 512
#define D 1024
#define H 1024
#define G 4096  // 4*H

// Persistent step kernel: 128 CTAs, each owns 32 gate rows (4 gates x 8 hid)
#define NCTA 128
#define THREADS 256
// Weight slab per CTA: 128 ksteps * 2 mblk * 32 lanes * 16B = 8192 uint4 = 128KB
#define W_SLAB_UINT4 8192
#define SG_STRIDE 66
#define DYN_SMEM_BYTES (W_SLAB_UINT4 * 16 + 32 * SG_STRIDE * 4)  // 139520

// xproj tensor-core GEMM geometry
#define XP_BM 128
#define XP_BN 128
#define XP_NMT (B * S / XP_BM)   // 256 m-tiles
#define XP_NNT (G / XP_BN)       // 32 n-tiles
#define XP_CHUNK_U4 1024         // one BK=32 chunk = 4 ksteps*8 blk*32 lanes = 16KB
#define XP_SMEM_BYTES (4 * XP_CHUNK_U4 * 16)  // 64KB (A,B double buffered)

// Device scratch (no allocation allowed)
__device__ float    g_xproj[(size_t)B * S * G];                  // [B*S, 4H]
__device__ uint32_t g_wpack[(size_t)NCTA * W_SLAB_UINT4 * 4];    // Whh tf32, fragment-packed
__device__ uint32_t g_hpack[2][128 * 4 * 32 * 4];                // h tf32, fragment-packed (ping-pong)
__device__ float    g_c[B * H];                                  // cell state (start/end only)
__device__ unsigned g_bar;                                       // global step barrier
__device__ uint32_t g_xpack[(size_t)XP_NMT * 128 * 8 * 32 * 4];  // inputs tf32 A-frag-packed (128MB)
__device__ uint32_t g_wihpack[(size_t)XP_NNT * 128 * 8 * 32 * 4]; // Wih tf32 B-frag-packed (16MB)

// ---------------------------------------------------------------------------
// Helpers
// ---------------------------------------------------------------------------
__device__ __forceinline__ uint32_t smem_u32(const void* p) {
    uint32_t a;
    asm("{ .reg .u64 t; cvta.to.shared.u64 t, %1; cvt.u32.u64 %0, t; }"
        : "=r"(a) : "l"(p));
    return a;
}

__device__ __forceinline__ uint32_t f2tf32(float f) {
    uint32_t r;
    asm("cvt.rna.tf32.f32 %0, %1;" : "=r"(r) : "f"(f));
    return r;
}

#define CP_ASYNC16(dst, src) \
    asm volatile("cp.async.cg.shared.global [%0], [%1], 16;" :: "r"(dst), "l"(src) : "memory")
#define CP_COMMIT() asm volatile("cp.async.commit_group;" ::: "memory")
#define CP_WAIT(n)  asm volatile("cp.async.wait_group %0;" :: "n"(n) : "memory")

#define MMA_TF32(c0, c1, c2, c3, a0, a1, a2, a3, b0, b1)                     \
    asm volatile("mma.sync.aligned.m16n8k8.row.col.f32.tf32.tf32.f32 "       \
                 "{%0,%1,%2,%3}, {%4,%5,%6,%7}, {%8,%9}, {%0,%1,%2,%3};"     \
                 : "+f"(c0), "+f"(c1), "+f"(c2), "+f"(c3)                    \
                 : "r"(a0), "r"(a1), "r"(a2), "r"(a3), "r"(b0), "r"(b1))

// ---------------------------------------------------------------------------
// Whh prep (unchanged): tf32 per-lane A-fragment order for the step kernel.
// ---------------------------------------------------------------------------
__global__ void prep_wpack(const float* __restrict__ whh) {
    int idx = blockIdx.x * 256 + threadIdx.x;   // 0 .. 4M-1
    int a     = idx & 3;
    int lane  = (idx >> 2) & 31;
    int mblk  = (idx >> 7) & 1;
    int kstep = (idx >> 8) & 127;
    int ct    = idx >> 15;

    int row16 = (lane >> 2) + 8 * (a & 1);
    int kofs  = (lane & 3) + 4 * (a >> 1);
    int r = mblk * 16 + row16;
    int q = r >> 3;
    int j = r & 7;
    int grow = q * H + ct * 8 + j;
    int k = kstep * 8 + kofs;
    g_wpack[idx] = f2tf32(whh[(size_t)grow * H + k]);
}

// ---------------------------------------------------------------------------
// xproj A-pack: inputs [B*S, D] fp32 -> tf32 A-fragment order.
// Layout: [mtile(256)][kstep(128)][mblk(8)][lane(32)][a(4)]
//   row = mtile*128 + mblk*16 + lane/4 + 8*(a&1); k = kstep*8 + lane%4 + 4*(a>>1)
// ---------------------------------------------------------------------------
__global__ void prep_xpack(const float* __restrict__ inp) {
    int idx = blockIdx.x * 256 + threadIdx.x;   // 0 .. 32M-1
    int a     = idx & 3;
    int lane  = (idx >> 2) & 31;
    int mblk  = (idx >> 7) & 7;
    int kstep = (idx >> 10) & 127;
    int mtile = idx >> 17;

    int m = mtile * 128 + mblk * 16 + (lane >> 2) + 8 * (a & 1);
    int k = kstep * 8 + (lane & 3) + 4 * (a >> 1);
    g_xpack[idx] = f2tf32(inp[(size_t)m * D + k]);
}

// ---------------------------------------------------------------------------
// xproj B-pack: Wih [G, D] fp32 -> tf32 B-fragment order (paired n8 blocks).
// Layout: [ntile(32)][kstep(128)][npair(8)][lane(32)][w(4)], w = nsub*2 + b
//   n = ntile*128 + npair*16 + nsub*8 + lane/4; k = kstep*8 + lane%4 + 4*b
// ---------------------------------------------------------------------------
__global__ void prep_wihpack(const float* __restrict__ wih) {
    int idx = blockIdx.x * 256 + threadIdx.x;   // 0 .. 4M-1
    int w     = idx & 3;
    int lane  = (idx >> 2) & 31;
    int npair = (idx >> 7) & 7;
    int kstep = (idx >> 10) & 127;
    int ntile = idx >> 17;

    int nsub = w >> 1, bsel = w & 1;
    int n = ntile * 128 + npair * 16 + nsub * 8 + (lane >> 2);
    int k = kstep * 8 + (lane & 3) + 4 * bsel;
    g_wihpack[idx] = f2tf32(wih[(size_t)n * D + k]);
}

// ---------------------------------------------------------------------------
// hpack addressing (unchanged)
// ---------------------------------------------------------------------------
__device__ __forceinline__ uint32_t hpack_addr(int b, int hid) {
    int kstep = hid >> 3, kk = hid & 7;
    int khalf = kk >> 2, kfrac = kk & 3;
    int nblk = b >> 4, rem = b & 15;
    int jb = rem >> 3, trow = rem & 7;
    int lane = trow * 4 + kfrac;
    int f = khalf * 2 + jb;
    return (uint32_t)(((kstep * 4 + nblk) * 32 + lane) * 4 + f);
}

__global__ void init_state(const float* __restrict__ h0,
                           const float* __restrict__ c0) {
    int i = blockIdx.x * blockDim.x + threadIdx.x;
    if (i == 0) g_bar = 0u;
    if (i < B * H) {
        g_c[i] = c0[i];
        int b = i >> 10, hid = i & 1023;
        g_hpack[0][hpack_addr(b, hid)] = f2tf32(h0[i]);
    }
}

// ---------------------------------------------------------------------------
// xproj GEMM on tensor cores: C[32768, 4096] = A @ Wih^T + bias_ih.
// CTA tile 128x128, BK=32, cp.async double buffer, 8 warps (m64 x n32 each).
// Operands pre-packed in fragment order -> mainloop is LDS.128 + HMMA only.
// ---------------------------------------------------------------------------
__global__ void __launch_bounds__(256, 2)
xproj_mma(const float* __restrict__ bias) {
    extern __shared__ __align__(16) uint4 xsm[];
    // [0:1024) A buf0 | [1024:2048) A buf1 | [2048:3072) B buf0 | [3072:4096) B buf1
    uint32_t aAddr[2] = { smem_u32(xsm), smem_u32(xsm + XP_CHUNK_U4) };
    uint32_t bAddr[2] = { smem_u32(xsm + 2 * XP_CHUNK_U4), smem_u32(xsm + 3 * XP_CHUNK_U4) };

    int tid = threadIdx.x;
    int wid = tid >> 5;
    int lane = tid & 31;
    int wm = wid & 1;          // m-warp (0..1): rows wm*64
    int wn = wid >> 1;         // n-warp (0..3): cols wn*32
    int mtile = blockIdx.y;
    int ntile = blockIdx.x;

    const uint4* gA = (const uint4*)g_xpack + (size_t)mtile * (128 * 8 * 32);
    const uint4* gB = (const uint4*)g_wihpack + (size_t)ntile * (128 * 8 * 32);

    float acc[4][4][4] = {};

    // Prologue: chunk 0
#pragma unroll
    for (int i = 0; i < 4; i++) {
        int l = tid + i * 256;
        CP_ASYNC16(aAddr[0] + l * 16, (const char*)gA + l * 16);
        CP_ASYNC16(bAddr[0] + l * 16, (const char*)gB + l * 16);
    }
    CP_COMMIT();

    for (int ki = 0; ki < 32; ki++) {
        if (ki + 1 < 32) {
            int nb = (ki + 1) & 1;
            const char* srcA = (const char*)(gA + (size_t)(ki + 1) * XP_CHUNK_U4);
            const char* srcB = (const char*)(gB + (size_t)(ki + 1) * XP_CHUNK_U4);
#pragma unroll
            for (int i = 0; i < 4; i++) {
                int l = tid + i * 256;
                CP_ASYNC16(aAddr[nb] + l * 16, srcA + l * 16);
                CP_ASYNC16(bAddr[nb] + l * 16, srcB + l * 16);
            }
            CP_COMMIT();
            CP_WAIT(1);
        } else {
            CP_WAIT(0);
        }
        __syncthreads();

        const uint4* cA = xsm + (ki & 1) * XP_CHUNK_U4;
        const uint4* cB = xsm + (2 + (ki & 1)) * XP_CHUNK_U4;
#pragma unroll
        for (int ks = 0; ks < 4; ks++) {
            uint4 av[4], bv[2];
#pragma unroll
            for (int m = 0; m < 4; m++)
                av[m] = cA[ks * 256 + (wm * 4 + m) * 32 + lane];
#pragma unroll
            for (int p = 0; p < 2; p++)
                bv[p] = cB[ks * 256 + (wn * 2 + p) * 32 + lane];
#pragma unroll
            for (int m = 0; m < 4; m++) {
                MMA_TF32(acc[m][0][0], acc[m][0][1], acc[m][0][2], acc[m][0][3],
                         av[m].x, av[m].y, av[m].z, av[m].w, bv[0].x, bv[0].y);
                MMA_TF32(acc[m][1][0], acc[m][1][1], acc[m][1][2], acc[m][1][3],
                         av[m].x, av[m].y, av[m].z, av[m].w, bv[0].z, bv[0].w);
                MMA_TF32(acc[m][2][0], acc[m][2][1], acc[m][2][2], acc[m][2][3],
                         av[m].x, av[m].y, av[m].z, av[m].w, bv[1].x, bv[1].y);
                MMA_TF32(acc[m][3][0], acc[m][3][1], acc[m][3][2], acc[m][3][3],
                         av[m].x, av[m].y, av[m].z, av[m].w, bv[1].z, bv[1].w);
            }
        }
        __syncthreads();
    }

    // Epilogue: bias + store. C frag: (row=lane/4, col=2*(lane%4)) c0,c1; +8 rows c2,c3.
#pragma unroll
    for (int m = 0; m < 4; m++) {
        int row = mtile * 128 + wm * 64 + m * 16 + (lane >> 2);
#pragma unroll
        for (int j = 0; j < 4; j++) {
            int col = ntile * 128 + wn * 32 + j * 8 + (lane & 3) * 2;
            float b0 = bias[col], b1 = bias[col + 1];
            *(float2*)&g_xproj[(size_t)row * G + col] =
                make_float2(acc[m][j][0] + b0, acc[m][j][1] + b1);
            *(float2*)&g_xproj[(size_t)(row + 8) * G + col] =
                make_float2(acc[m][j][2] + b0, acc[m][j][3] + b1);
        }
    }
}

// ---------------------------------------------------------------------------
// Persistent LSTM (unchanged from round 6)
// ---------------------------------------------------------------------------
__global__ void __launch_bounds__(THREADS, 1)
lstm_persist(const float* __restrict__ bias_hh, float* __restrict__ out) {
    extern __shared__ __align__(16) uint4 smem4[];
    uint4* sW = smem4;                              // 8192 uint4 weight slab
    float* sG = (float*)(smem4 + W_SLAB_UINT4);     // 32 x 66 exchange

    int tid = threadIdx.x;
    int wid = tid >> 5;
    int lane = tid & 31;
    int bx = blockIdx.x;
    int mblk = wid & 1;
    int nblk = wid >> 1;

    const uint4* gW = (const uint4*)g_wpack + (size_t)bx * W_SLAB_UINT4;
#pragma unroll
    for (int i = 0; i < W_SLAB_UINT4 / THREADS; i++)
        sW[tid + i * THREADS] = gW[tid + i * THREADS];

    int j = tid & 7;
    int b0 = tid >> 3;            // 0..31
    int hid = bx * 8 + j;
    float bi0 = bias_hh[hid];
    float bi1 = bias_hh[H + hid];
    float bi2 = bias_hh[2 * H + hid];
    float bi3 = bias_hh[3 * H + hid];
    float creg0 = g_c[b0 * H + hid];
    float creg1 = g_c[(b0 + 32) * H + hid];

    __syncthreads();

    int bIdx = nblk * 32 + lane;
    int aBase = mblk * 32 + lane;

    for (int t = 0; t < S; t++) {
        size_t xb0 = ((size_t)b0 * S + t) * G + hid;
        size_t xb1 = ((size_t)(b0 + 32) * S + t) * G + hid;
        float xp00 = __ldg(&g_xproj[xb0]);
        float xp01 = __ldg(&g_xproj[xb0 + H]);
        float xp02 = __ldg(&g_xproj[xb0 + 2 * H]);
        float xp03 = __ldg(&g_xproj[xb0 + 3 * H]);
        float xp10 = __ldg(&g_xproj[xb1]);
        float xp11 = __ldg(&g_xproj[xb1 + H]);
        float xp12 = __ldg(&g_xproj[xb1 + 2 * H]);
        float xp13 = __ldg(&g_xproj[xb1 + 3 * H]);

        const uint4* gB4 = (const uint4*)g_hpack[t & 1];

        float c00 = 0.f, c01 = 0.f, c02 = 0.f, c03 = 0.f;
        float c10 = 0.f, c11 = 0.f, c12 = 0.f, c13 = 0.f;

        uint4 bvA[8], bvB[8];
#pragma unroll
        for (int k = 0; k < 8; k++) bvA[k] = __ldcg(&gB4[k * 128 + bIdx]);

#pragma unroll 1
        for (int ks0 = 0; ks0 < 128; ks0 += 16) {
#pragma unroll
            for (int k = 0; k < 8; k++)
                bvB[k] = __ldcg(&gB4[(ks0 + 8 + k) * 128 + bIdx]);
#pragma unroll
            for (int k = 0; k < 8; k++) {
                uint4 av = sW[(ks0 + k) * 64 + aBase];
                MMA_TF32(c00, c01, c02, c03, av.x, av.y, av.z, av.w, bvA[k].x, bvA[k].z);
                MMA_TF32(c10, c11, c12, c13, av.x, av.y, av.z, av.w, bvA[k].y, bvA[k].w);
            }
            if (ks0 + 16 < 128) {
#pragma unroll
                for (int k = 0; k < 8; k++)
                    bvA[k] = __ldcg(&gB4[(ks0 + 16 + k) * 128 + bIdx]);
            }
#pragma unroll
            for (int k = 0; k < 8; k++) {
                uint4 av = sW[(ks0 + 8 + k) * 64 + aBase];
                MMA_TF32(c00, c01, c02, c03, av.x, av.y, av.z, av.w, bvB[k].x, bvB[k].z);
                MMA_TF32(c10, c11, c12, c13, av.x, av.y, av.z, av.w, bvB[k].y, bvB[k].w);
            }
        }

        {
            int r0 = mblk * 16 + (lane >> 2);
            int col = nblk * 16 + (lane & 3) * 2;
            *(float2*)&sG[r0 * SG_STRIDE + col]           = make_float2(c00, c01);
            *(float2*)&sG[(r0 + 8) * SG_STRIDE + col]     = make_float2(c02, c03);
            *(float2*)&sG[r0 * SG_STRIDE + col + 8]       = make_float2(c10, c11);
            *(float2*)&sG[(r0 + 8) * SG_STRIDE + col + 8] = make_float2(c12, c13);
        }
        __syncthreads();

        uint32_t* hnext = g_hpack[(t + 1) & 1];
        {
            float gi = sG[(0 * 8 + j) * SG_STRIDE + b0] + xp00 + bi0;
            float gf = sG[(1 * 8 + j) * SG_STRIDE + b0] + xp01 + bi1;
            float gg = sG[(2 * 8 + j) * SG_STRIDE + b0] + xp02 + bi2;
            float go = sG[(3 * 8 + j) * SG_STRIDE + b0] + xp03 + bi3;
            float iv = 1.0f / (1.0f + expf(-gi));
            float fv = 1.0f / (1.0f + expf(-gf));
            float gv = tanhf(gg);
            float ov = 1.0f / (1.0f + expf(-go));
            creg0 = fv * creg0 + iv * gv;
            float hv = ov * tanhf(creg0);
            out[((size_t)b0 * S + t) * H + hid] = hv;
            hnext[hpack_addr(b0, hid)] = f2tf32(hv);
        }
        {
            float gi = sG[(0 * 8 + j) * SG_STRIDE + b0 + 32] + xp10 + bi0;
            float gf = sG[(1 * 8 + j) * SG_STRIDE + b0 + 32] + xp11 + bi1;
            float gg = sG[(2 * 8 + j) * SG_STRIDE + b0 + 32] + xp12 + bi2;
            float go = sG[(3 * 8 + j) * SG_STRIDE + b0 + 32] + xp13 + bi3;
            float iv = 1.0f / (1.0f + expf(-gi));
            float fv = 1.0f / (1.0f + expf(-gf));
            float gv = tanhf(gg);
            float ov = 1.0f / (1.0f + expf(-go));
            creg1 = fv * creg1 + iv * gv;
            float hv = ov * tanhf(creg1);
            out[((size_t)(b0 + 32) * S + t) * H + hid] = hv;
            hnext[hpack_addr(b0 + 32, hid)] = f2tf32(hv);
        }

        __threadfence();
        __syncthreads();
        if (tid == 0) {
            atomicAdd(&g_bar, 1u);
            unsigned target = (unsigned)(NCTA * (t + 1));
            while (atomicAdd(&g_bar, 0u) < target) {
                __nanosleep(32);
            }
            __threadfence();
        }
        __syncthreads();
    }

    g_c[b0 * H + hid] = creg0;
    g_c[(b0 + 32) * H + hid] = creg1;
}

// ---------------------------------------------------------------------------
// Finalize: hn = out[:, S-1, :], cn = g_c
// ---------------------------------------------------------------------------
__global__ void finalize(float* __restrict__ out) {
    int i = blockIdx.x * blockDim.x + threadIdx.x;
    if (i < B * H) {
        int b = i >> 10, hid = i & 1023;
        size_t tail = (size_t)B * S * H;
        out[tail + i] = out[((size_t)b * S + (S - 1)) * H + hid];
        out[tail + (size_t)B * H + i] = g_c[i];
    }
}

// ---------------------------------------------------------------------------
// Launch
// ---------------------------------------------------------------------------
extern "C" void kernel_launch(void* const* d_in, const int* in_sizes, int n_in,
                              void* d_out, int out_size) {
    (void)in_sizes; (void)n_in; (void)out_size;

    const float* inputs = (const float*)d_in[0];  // [B, S, D]
    const float* h0     = (const float*)d_in[1];  // [1, B, H]
    const float* c0     = (const float*)d_in[2];  // [1, B, H]
    const float* wih    = (const float*)d_in[3];  // [4H, D]
    const float* whh    = (const float*)d_in[4];  // [4H, H]
    const float* bih    = (const float*)d_in[5];  // [4H]
    const float* bhh    = (const float*)d_in[6];  // [4H]
    float* out = (float*)d_out;

    cudaFuncSetAttribute(lstm_persist,
                         cudaFuncAttributeMaxDynamicSharedMemorySize,
                         DYN_SMEM_BYTES);
    cudaFuncSetAttribute(xproj_mma,
                         cudaFuncAttributeMaxDynamicSharedMemorySize,
                         XP_SMEM_BYTES);

    init_state<<<(B * H + 255) / 256, 256>>>(h0, c0);
    prep_wpack<<<(G * H) / 256, 256>>>(whh);
    prep_xpack<<<(B * S * D) / 256, 256>>>(inputs);
    prep_wihpack<<<(G * D) / 256, 256>>>(wih);

    dim3 gx(XP_NNT, XP_NMT);  // 32 x 256
    xproj_mma<<<gx, 256, XP_SMEM_BYTES>>>(bih);

    lstm_persist<<<NCTA, THREADS, DYN_SMEM_BYTES>>>(bhh, out);

    finalize<<<(B * H + 255) / 256, 256>>>(out);
}